// round 9
// baseline (speedup 1.0000x reference)
#include <cuda_runtime.h>
#include <cuda_fp16.h>
#include <cstdint>

#define B_   8
#define S_   4096
#define D_HD 64
#define BQ   128
#define BK   128
#define NTH  256

// Q pre-scale: (1/sqrt(64)) * log2(e)  -> scores arrive in log2 domain
#define QSCALE 0.18033688011112042f

// ---- 3-stage pipelined smem: stage = KF(18432) + VF(18432) ----
#define STAGE_BYTES 36864
#define OFF_KF 0
#define OFF_VF 18432
#define SM_RS  (3 * STAGE_BYTES)        // float[128]
#define SM_TOT (3 * STAGE_BYTES + 512)
#define QS_STRIDE 68

// fp16 K/V in tile-ready layout: [b*S + row][72 halves] (144B row stride)
#define GROW 72
__device__ __align__(16) __half g_kf[(size_t)B_ * S_ * GROW];
__device__ __align__(16) __half g_vf[(size_t)B_ * S_ * GROW];
// unnormalized exp(scores) in fp16: [b*S + q][S]  (268 MB scratch)
__device__ __align__(16) __half g_pf[(size_t)B_ * S_ * S_];

static __device__ __forceinline__ uint32_t smem_u32(const void* p) {
    uint32_t a;
    asm("{ .reg .u64 t; cvta.to.shared.u64 t, %1; cvt.u32.u64 %0, t; }" : "=r"(a) : "l"(p));
    return a;
}
static __device__ __forceinline__ void ldsm4(uint32_t* r, uint32_t addr) {
    asm volatile("ldmatrix.sync.aligned.m8n8.x4.shared.b16 {%0,%1,%2,%3}, [%4];"
                 : "=r"(r[0]), "=r"(r[1]), "=r"(r[2]), "=r"(r[3]) : "r"(addr));
}
static __device__ __forceinline__ void ldsm4t(uint32_t* r, uint32_t addr) {
    asm volatile("ldmatrix.sync.aligned.m8n8.x4.trans.shared.b16 {%0,%1,%2,%3}, [%4];"
                 : "=r"(r[0]), "=r"(r[1]), "=r"(r[2]), "=r"(r[3]) : "r"(addr));
}
static __device__ __forceinline__ void mma_f16(float* c, const uint32_t* a,
                                               uint32_t b0, uint32_t b1) {
    asm volatile("mma.sync.aligned.m16n8k16.row.col.f32.f16.f16.f32 "
                 "{%0,%1,%2,%3}, {%4,%5,%6,%7}, {%8,%9}, {%0,%1,%2,%3};"
                 : "+f"(c[0]), "+f"(c[1]), "+f"(c[2]), "+f"(c[3])
                 : "r"(a[0]), "r"(a[1]), "r"(a[2]), "r"(a[3]), "r"(b0), "r"(b1));
}
static __device__ __forceinline__ uint32_t packhf(float a, float b) {
    __half2 t = __floats2half2_rn(a, b);
    return *reinterpret_cast<uint32_t*>(&t);
}
static __device__ __forceinline__ float ex2(float x) {
    float r;
    asm("ex2.approx.f32 %0, %1;" : "=f"(r) : "f"(x));
    return r;
}

// ---- one-time convert of K/V to fp16 in tile-ready layout ----
__global__ __launch_bounds__(256)
void prep_half_kernel(const float* __restrict__ K, const float* __restrict__ V)
{
    size_t idx = (size_t)blockIdx.x * 256 + threadIdx.x;   // float4 index
    size_t row = idx >> 4;
    int d4 = (int)(idx & 15);
    size_t dst = row * GROW + (size_t)d4 * 4;

    float4 kv = reinterpret_cast<const float4*>(K)[idx];
    *reinterpret_cast<uint2*>(&g_kf[dst]) =
        make_uint2(packhf(kv.x, kv.y), packhf(kv.z, kv.w));
    float4 vv = reinterpret_cast<const float4*>(V)[idx];
    *reinterpret_cast<uint2*>(&g_vf[dst]) =
        make_uint2(packhf(vv.x, vv.y), packhf(vv.z, vv.w));
}

__global__ __launch_bounds__(NTH, 2)
void attn_hmma_kernel(const float* __restrict__ Q,
                      const int*   __restrict__ mask,
                      float* __restrict__ ctx_out,
                      float* __restrict__ attn_out)
{
    extern __shared__ char smc[];
    const uint32_t sb = smem_u32(smc);

    const int tid  = threadIdx.x;
    const int w    = tid >> 5;          // warp owns q-rows [16w, 16w+16)
    const int lane = tid & 31;
    const int lrow = lane & 7;
    const int lsub = lane >> 3;
    const int b    = blockIdx.y;
    const int q0   = blockIdx.x * BQ;

    const uint32_t kofsB = (uint32_t)((((lsub & 2) ? 8 : 0) + lrow) * 144 + ((lsub & 1) ? 16 : 0));
    const uint32_t kofsV = (uint32_t)((lrow + ((lsub & 1) ? 8 : 0)) * 144 + ((lsub & 2) ? 16 : 0));

    // async copy of one k-tile (KF + VF, each 1152 x 16B) into a stage
    auto issue_copy = [&](int t, int stg) {
        size_t gbase = ((size_t)b * S_ + (size_t)t * BK) * GROW;
        const __half* gp[2] = { g_kf + gbase, g_vf + gbase };
        uint32_t s0 = sb + (uint32_t)stg * STAGE_BYTES;
        #pragma unroll
        for (int a = 0; a < 2; ++a) {
            uint64_t ga = (uint64_t)__cvta_generic_to_global(gp[a]);
            uint32_t sa = s0 + (uint32_t)a * 18432u;
            #pragma unroll
            for (int i = 0; i < 4; ++i) {
                uint32_t o = (uint32_t)(tid + i * NTH) * 16u;
                asm volatile("cp.async.cg.shared.global [%0], [%1], 16;"
                             :: "r"(sa + o), "l"(ga + o));
            }
            if (tid < 128) {
                uint32_t o = (uint32_t)(1024 + tid) * 16u;
                asm volatile("cp.async.cg.shared.global [%0], [%1], 16;"
                             :: "r"(sa + o), "l"(ga + o));
            }
        }
        asm volatile("cp.async.commit_group;" ::: "memory");
    };

    // prologue: tiles 0,1 in flight; Q (scaled) staged in stage-2 slot
    issue_copy(0, 0);
    issue_copy(1, 1);
    {
        float* smf = reinterpret_cast<float*>(smc + 2 * STAGE_BYTES);
        const float* Qg = Q + ((size_t)b * S_ + q0) * D_HD;
        #pragma unroll
        for (int it = 0; it < 8; ++it) {
            int idx = (it * NTH + tid) * 4;
            int q = idx >> 6, d = idx & 63;
            float4 v = *reinterpret_cast<const float4*>(Qg + idx);
            float* dst = smf + q * QS_STRIDE + d;
            dst[0] = v.x * QSCALE; dst[1] = v.y * QSCALE;
            dst[2] = v.z * QSCALE; dst[3] = v.w * QSCALE;
        }
    }
    __syncthreads();

    // persistent fp16 Q A-fragments (16 regs)
    uint32_t qf[4][4];
    {
        const float* smf = reinterpret_cast<const float*>(smc + 2 * STAGE_BYTES);
        const int r0 = 16 * w + (lane >> 2);
        const int c0 = 2 * (lane & 3);
        #pragma unroll
        for (int kc = 0; kc < 4; ++kc) {
            #pragma unroll
            for (int f = 0; f < 4; ++f) {
                int rr = r0 + ((f & 1) ? 8 : 0);
                int cc = kc * 16 + c0 + ((f & 2) ? 8 : 0);
                float2 v = *reinterpret_cast<const float2*>(smf + rr * QS_STRIDE + cc);
                qf[kc][f] = packhf(v.x, v.y);
            }
        }
    }
    __syncthreads();   // Q staging done; stage-2 free for the pipeline

    float ctx[8][4];
    #pragma unroll
    for (int i = 0; i < 8; ++i)
        #pragma unroll
        for (int j = 0; j < 4; ++j) ctx[i][j] = 0.0f;
    float rs0 = 0.0f, rs1 = 0.0f;

    const size_t rowA = (size_t)b * S_ + q0 + 16 * w + (lane >> 2);
    const int    colL = 2 * (lane & 3);

    for (int t = 0; t < S_ / BK; ++t) {
        const int k0 = t << 7;

        if (t < S_ / BK - 1)
            asm volatile("cp.async.wait_group 1;" ::: "memory");
        else
            asm volatile("cp.async.wait_group 0;" ::: "memory");
        __syncthreads();                        // tile t resident
        if (t + 2 < S_ / BK) issue_copy(t + 2, (t + 2) % 3);

        const uint32_t base = sb + (uint32_t)(t % 3) * STAGE_BYTES;

        #pragma unroll
        for (int h = 0; h < 2; ++h) {
            const size_t cbase = (size_t)(k0 + h * 64 + colL);

            // ---- prefetch mask batch A (nt 0..3) before the MMA block ----
            int2 mA[8];
            #pragma unroll
            for (int nt = 0; nt < 4; ++nt) {
                mA[2*nt]   = *reinterpret_cast<const int2*>(mask + rowA * S_ + cbase + nt * 8);
                mA[2*nt+1] = *reinterpret_cast<const int2*>(mask + (rowA + 8) * S_ + cbase + nt * 8);
            }

            // ---- QK^T half: single-pass fp16 (scores in log2 domain) ----
            float sc[8][4];
            #pragma unroll
            for (int i = 0; i < 8; ++i)
                #pragma unroll
                for (int j = 0; j < 4; ++j) sc[i][j] = 0.0f;

            const uint32_t bbase = base + OFF_KF + (uint32_t)(h * 9216) + kofsB;
            #pragma unroll
            for (int kc = 0; kc < 4; ++kc) {
                #pragma unroll
                for (int ntp = 0; ntp < 4; ++ntp) {
                    uint32_t bfr[4];
                    ldsm4(bfr, bbase + (uint32_t)(ntp * 2304 + kc * 32));
                    mma_f16(sc[2 * ntp],     qf[kc], bfr[0], bfr[1]);
                    mma_f16(sc[2 * ntp + 1], qf[kc], bfr[2], bfr[3]);
                }
            }

            // ---- prefetch mask batch B (nt 4..7), consumed last ----
            int2 mB[8];
            #pragma unroll
            for (int nt = 0; nt < 4; ++nt) {
                mB[2*nt]   = *reinterpret_cast<const int2*>(mask + rowA * S_ + cbase + (nt + 4) * 8);
                mB[2*nt+1] = *reinterpret_cast<const int2*>(mask + (rowA + 8) * S_ + cbase + (nt + 4) * 8);
            }

            // ---- mask + ex2 + fp16 scratch write; P fragments reuse packs ----
            uint32_t pf[4][4];
            #pragma unroll
            for (int nt = 0; nt < 8; ++nt) {
                const int2 m0 = (nt < 4) ? mA[2*nt]   : mB[2*(nt-4)];
                const int2 m1 = (nt < 4) ? mA[2*nt+1] : mB[2*(nt-4)+1];
                const size_t cg = cbase + (size_t)nt * 8;
                float e0 = m0.x ? 0.0f : ex2(sc[nt][0]);
                float e1 = m0.y ? 0.0f : ex2(sc[nt][1]);
                float e2 = m1.x ? 0.0f : ex2(sc[nt][2]);
                float e3 = m1.y ? 0.0f : ex2(sc[nt][3]);
                rs0 += e0 + e1; rs1 += e2 + e3;
                uint32_t u01 = packhf(e0, e1);
                uint32_t u23 = packhf(e2, e3);
                *reinterpret_cast<uint32_t*>(g_pf + rowA * S_ + cg)       = u01;
                *reinterpret_cast<uint32_t*>(g_pf + (rowA + 8) * S_ + cg) = u23;
                const int fb = (nt & 1) ? 2 : 0;
                pf[nt >> 1][fb]     = u01;
                pf[nt >> 1][fb + 1] = u23;
            }

            // ---- P·V half: single-pass fp16, k-slice h ----
            const uint32_t vbase = base + OFF_VF + (uint32_t)(h * 9216) + kofsV;
            #pragma unroll
            for (int kcp = 0; kcp < 4; ++kcp) {
                #pragma unroll
                for (int ntp = 0; ntp < 4; ++ntp) {
                    uint32_t vf[4];
                    ldsm4t(vf, vbase + (uint32_t)(kcp * 2304 + ntp * 32));
                    mma_f16(ctx[2 * ntp],     pf[kcp], vf[0], vf[1]);
                    mma_f16(ctx[2 * ntp + 1], pf[kcp], vf[2], vf[3]);
                }
            }
        }
    }

    // ---- rowsums -> smem, invert once ----
    rs0 += __shfl_xor_sync(0xffffffffu, rs0, 1);
    rs0 += __shfl_xor_sync(0xffffffffu, rs0, 2);
    rs1 += __shfl_xor_sync(0xffffffffu, rs1, 1);
    rs1 += __shfl_xor_sync(0xffffffffu, rs1, 2);
    __syncthreads();
    float* rsum = reinterpret_cast<float*>(smc + SM_RS);
    if ((lane & 3) == 0) {
        rsum[16 * w + (lane >> 2)]     = rs0;
        rsum[16 * w + (lane >> 2) + 8] = rs1;
    }
    __syncthreads();
    if (tid < BQ) rsum[tid] = 1.0f / rsum[tid];
    __syncthreads();

    // ---- normalized ctx out ----
    const float inv0 = rsum[16 * w + (lane >> 2)];
    const float inv1 = rsum[16 * w + (lane >> 2) + 8];
    #pragma unroll
    for (int nt = 0; nt < 8; ++nt) {
        int d = nt * 8 + colL;
        *reinterpret_cast<float2*>(ctx_out + rowA * D_HD + d) =
            make_float2(ctx[nt][0] * inv0, ctx[nt][1] * inv0);
        *reinterpret_cast<float2*>(ctx_out + (rowA + 8) * D_HD + d) =
            make_float2(ctx[nt][2] * inv1, ctx[nt][3] * inv1);
    }

    // ---- fused normalize: this block's pf strip -> fp32 attn ----
    const __half* pfb = g_pf + ((size_t)b * S_ + q0) * S_;
    float* ab = attn_out + ((size_t)b * S_ + q0) * S_;
    #pragma unroll 4
    for (int i = tid; i < BQ * (S_ / 8); i += NTH) {
        int row = i >> 9;                   // 512 8-half chunks per row
        int ch  = (i & 511) << 3;
        float s = rsum[row];
        uint4 v = *reinterpret_cast<const uint4*>(pfb + (size_t)row * S_ + ch);
        float2 f0 = __half22float2(*reinterpret_cast<__half2*>(&v.x));
        float2 f1 = __half22float2(*reinterpret_cast<__half2*>(&v.y));
        float2 f2 = __half22float2(*reinterpret_cast<__half2*>(&v.z));
        float2 f3 = __half22float2(*reinterpret_cast<__half2*>(&v.w));
        float4* out = reinterpret_cast<float4*>(ab + (size_t)row * S_ + ch);
        out[0] = make_float4(f0.x * s, f0.y * s, f1.x * s, f1.y * s);
        out[1] = make_float4(f2.x * s, f2.y * s, f3.x * s, f3.y * s);
    }
}

extern "C" void kernel_launch(void* const* d_in, const int* in_sizes, int n_in,
                              void* d_out, int out_size)
{
    const float* Q = (const float*)d_in[0];
    const float* K = (const float*)d_in[1];
    const float* V = (const float*)d_in[2];
    const int* mask = (const int*)d_in[3];

    float* ctx_out  = (float*)d_out;
    float* attn_out = ctx_out + (size_t)B_ * S_ * D_HD;

    static bool attr_set = false;
    if (!attr_set) {
        cudaFuncSetAttribute(attn_hmma_kernel,
                             cudaFuncAttributeMaxDynamicSharedMemorySize, SM_TOT);
        attr_set = true;
    }

    prep_half_kernel<<<(B_ * S_ * D_HD / 4) / 256, 256>>>(K, V);
    dim3 grid(S_ / BQ, B_);
    attn_hmma_kernel<<<grid, NTH, SM_TOT>>>(Q, mask, ctx_out, attn_out);
}

// round 10
// speedup vs baseline: 1.0068x; 1.0068x over previous
#include <cuda_runtime.h>
#include <cuda_fp16.h>
#include <cstdint>

#define B_   8
#define S_   4096
#define D_HD 64
#define BQ   128
#define BK   128
#define NTH  256
#define KSPLIT 2
#define TILES_PER (S_ / BK / KSPLIT)    // 16

// Q pre-scale: (1/sqrt(64)) * log2(e)  -> scores arrive in log2 domain
#define QSCALE 0.18033688011112042f

// ---- 3-stage pipelined smem: stage = KF(18432) + VF(18432) ----
#define STAGE_BYTES 36864
#define OFF_KF 0
#define OFF_VF 18432
#define SM_RS  (3 * STAGE_BYTES)        // float[128]
#define SM_TOT (3 * STAGE_BYTES + 512)
#define QS_STRIDE 68

// fp16 K/V in tile-ready layout: [b*S + row][72 halves] (144B row stride)
#define GROW 72
__device__ __align__(16) __half g_kf[(size_t)B_ * S_ * GROW];
__device__ __align__(16) __half g_vf[(size_t)B_ * S_ * GROW];
// unnormalized exp(scores) in fp16: [b*S + q][S]
__device__ __align__(16) __half g_pf[(size_t)B_ * S_ * S_];
// partial (unnormalized) ctx per k-split: [KSPLIT][B*S][64]
__device__ __align__(16) float g_ctxp[(size_t)KSPLIT * B_ * S_ * D_HD];
__device__ float g_rowsum[(size_t)B_ * S_];
__device__ int   g_done[B_ * (S_ / BQ)];

static __device__ __forceinline__ uint32_t smem_u32(const void* p) {
    uint32_t a;
    asm("{ .reg .u64 t; cvta.to.shared.u64 t, %1; cvt.u32.u64 %0, t; }" : "=r"(a) : "l"(p));
    return a;
}
static __device__ __forceinline__ void ldsm4(uint32_t* r, uint32_t addr) {
    asm volatile("ldmatrix.sync.aligned.m8n8.x4.shared.b16 {%0,%1,%2,%3}, [%4];"
                 : "=r"(r[0]), "=r"(r[1]), "=r"(r[2]), "=r"(r[3]) : "r"(addr));
}
static __device__ __forceinline__ void ldsm4t(uint32_t* r, uint32_t addr) {
    asm volatile("ldmatrix.sync.aligned.m8n8.x4.trans.shared.b16 {%0,%1,%2,%3}, [%4];"
                 : "=r"(r[0]), "=r"(r[1]), "=r"(r[2]), "=r"(r[3]) : "r"(addr));
}
static __device__ __forceinline__ void mma_f16(float* c, const uint32_t* a,
                                               uint32_t b0, uint32_t b1) {
    asm volatile("mma.sync.aligned.m16n8k16.row.col.f32.f16.f16.f32 "
                 "{%0,%1,%2,%3}, {%4,%5,%6,%7}, {%8,%9}, {%0,%1,%2,%3};"
                 : "+f"(c[0]), "+f"(c[1]), "+f"(c[2]), "+f"(c[3])
                 : "r"(a[0]), "r"(a[1]), "r"(a[2]), "r"(a[3]), "r"(b0), "r"(b1));
}
static __device__ __forceinline__ uint32_t packhf(float a, float b) {
    __half2 t = __floats2half2_rn(a, b);
    return *reinterpret_cast<uint32_t*>(&t);
}
static __device__ __forceinline__ float ex2(float x) {
    float r;
    asm("ex2.approx.f32 %0, %1;" : "=f"(r) : "f"(x));
    return r;
}

// ---- one-time K/V fp16 convert + per-launch zeroing of accumulators ----
__global__ __launch_bounds__(256)
void prep_half_kernel(const float* __restrict__ K, const float* __restrict__ V)
{
    size_t gid = (size_t)blockIdx.x * 256 + threadIdx.x;
    if (gid < (size_t)B_ * S_) g_rowsum[gid] = 0.0f;
    if (gid < B_ * (S_ / BQ))  g_done[gid] = 0;

    size_t idx = gid;                      // float4 index
    size_t row = idx >> 4;
    int d4 = (int)(idx & 15);
    size_t dst = row * GROW + (size_t)d4 * 4;

    float4 kv = reinterpret_cast<const float4*>(K)[idx];
    *reinterpret_cast<uint2*>(&g_kf[dst]) =
        make_uint2(packhf(kv.x, kv.y), packhf(kv.z, kv.w));
    float4 vv = reinterpret_cast<const float4*>(V)[idx];
    *reinterpret_cast<uint2*>(&g_vf[dst]) =
        make_uint2(packhf(vv.x, vv.y), packhf(vv.z, vv.w));
}

__global__ __launch_bounds__(NTH, 2)
void attn_hmma_kernel(const float* __restrict__ Q,
                      const int*   __restrict__ mask,
                      float* __restrict__ ctx_out,
                      float* __restrict__ attn_out)
{
    extern __shared__ char smc[];
    __shared__ int s_ticket;
    const uint32_t sb = smem_u32(smc);

    const int tid  = threadIdx.x;
    const int w    = tid >> 5;          // warp owns q-rows [16w, 16w+16)
    const int lane = tid & 31;
    const int lrow = lane & 7;
    const int lsub = lane >> 3;
    const int b    = blockIdx.y;
    const int q0   = blockIdx.x * BQ;
    const int z    = blockIdx.z;        // k-split half
    const int kt0  = z * TILES_PER;

    const uint32_t kofsB = (uint32_t)((((lsub & 2) ? 8 : 0) + lrow) * 144 + ((lsub & 1) ? 16 : 0));
    const uint32_t kofsV = (uint32_t)((lrow + ((lsub & 1) ? 8 : 0)) * 144 + ((lsub & 2) ? 16 : 0));

    // async copy of one k-tile (KF + VF, each 1152 x 16B) into a stage
    auto issue_copy = [&](int t, int stg) {
        size_t gbase = ((size_t)b * S_ + (size_t)t * BK) * GROW;
        const __half* gp[2] = { g_kf + gbase, g_vf + gbase };
        uint32_t s0 = sb + (uint32_t)stg * STAGE_BYTES;
        #pragma unroll
        for (int a = 0; a < 2; ++a) {
            uint64_t ga = (uint64_t)__cvta_generic_to_global(gp[a]);
            uint32_t sa = s0 + (uint32_t)a * 18432u;
            #pragma unroll
            for (int i = 0; i < 4; ++i) {
                uint32_t o = (uint32_t)(tid + i * NTH) * 16u;
                asm volatile("cp.async.cg.shared.global [%0], [%1], 16;"
                             :: "r"(sa + o), "l"(ga + o));
            }
            if (tid < 128) {
                uint32_t o = (uint32_t)(1024 + tid) * 16u;
                asm volatile("cp.async.cg.shared.global [%0], [%1], 16;"
                             :: "r"(sa + o), "l"(ga + o));
            }
        }
        asm volatile("cp.async.commit_group;" ::: "memory");
    };

    // prologue: tiles kt0, kt0+1 in flight; Q (scaled) staged in stage-2 slot
    issue_copy(kt0 + 0, 0);
    issue_copy(kt0 + 1, 1);
    {
        float* smf = reinterpret_cast<float*>(smc + 2 * STAGE_BYTES);
        const float* Qg = Q + ((size_t)b * S_ + q0) * D_HD;
        #pragma unroll
        for (int it = 0; it < 8; ++it) {
            int idx = (it * NTH + tid) * 4;
            int q = idx >> 6, d = idx & 63;
            float4 v = *reinterpret_cast<const float4*>(Qg + idx);
            float* dst = smf + q * QS_STRIDE + d;
            dst[0] = v.x * QSCALE; dst[1] = v.y * QSCALE;
            dst[2] = v.z * QSCALE; dst[3] = v.w * QSCALE;
        }
    }
    __syncthreads();

    // persistent fp16 Q A-fragments (16 regs)
    uint32_t qf[4][4];
    {
        const float* smf = reinterpret_cast<const float*>(smc + 2 * STAGE_BYTES);
        const int r0 = 16 * w + (lane >> 2);
        const int c0 = 2 * (lane & 3);
        #pragma unroll
        for (int kc = 0; kc < 4; ++kc) {
            #pragma unroll
            for (int f = 0; f < 4; ++f) {
                int rr = r0 + ((f & 1) ? 8 : 0);
                int cc = kc * 16 + c0 + ((f & 2) ? 8 : 0);
                float2 v = *reinterpret_cast<const float2*>(smf + rr * QS_STRIDE + cc);
                qf[kc][f] = packhf(v.x, v.y);
            }
        }
    }
    __syncthreads();   // Q staging done; stage-2 free for the pipeline

    float ctx[8][4];
    #pragma unroll
    for (int i = 0; i < 8; ++i)
        #pragma unroll
        for (int j = 0; j < 4; ++j) ctx[i][j] = 0.0f;
    float rs0 = 0.0f, rs1 = 0.0f;

    const size_t rowA = (size_t)b * S_ + q0 + 16 * w + (lane >> 2);
    const int    colL = 2 * (lane & 3);

    for (int tt = 0; tt < TILES_PER; ++tt) {
        const int k0 = (kt0 + tt) << 7;

        if (tt < TILES_PER - 1)
            asm volatile("cp.async.wait_group 1;" ::: "memory");
        else
            asm volatile("cp.async.wait_group 0;" ::: "memory");
        __syncthreads();                        // tile tt resident
        if (tt + 2 < TILES_PER) issue_copy(kt0 + tt + 2, (tt + 2) % 3);

        const uint32_t base = sb + (uint32_t)(tt % 3) * STAGE_BYTES;

        #pragma unroll
        for (int h = 0; h < 2; ++h) {
            // ---- QK^T half: single-pass fp16 (scores in log2 domain) ----
            float sc[8][4];
            #pragma unroll
            for (int i = 0; i < 8; ++i)
                #pragma unroll
                for (int j = 0; j < 4; ++j) sc[i][j] = 0.0f;

            const uint32_t bbase = base + OFF_KF + (uint32_t)(h * 9216) + kofsB;
            #pragma unroll
            for (int kc = 0; kc < 4; ++kc) {
                #pragma unroll
                for (int ntp = 0; ntp < 4; ++ntp) {
                    uint32_t bfr[4];
                    ldsm4(bfr, bbase + (uint32_t)(ntp * 2304 + kc * 32));
                    mma_f16(sc[2 * ntp],     qf[kc], bfr[0], bfr[1]);
                    mma_f16(sc[2 * ntp + 1], qf[kc], bfr[2], bfr[3]);
                }
            }

            // ---- mask + ex2 + fp16 scratch write; P fragments reuse packs ----
            uint32_t pf[4][4];
            #pragma unroll
            for (int nt = 0; nt < 8; ++nt) {
                const size_t cg = (size_t)(k0 + h * 64 + nt * 8 + colL);
                const int2 m0 = *reinterpret_cast<const int2*>(mask + rowA * S_ + cg);
                const int2 m1 = *reinterpret_cast<const int2*>(mask + (rowA + 8) * S_ + cg);
                float e0 = m0.x ? 0.0f : ex2(sc[nt][0]);
                float e1 = m0.y ? 0.0f : ex2(sc[nt][1]);
                float e2 = m1.x ? 0.0f : ex2(sc[nt][2]);
                float e3 = m1.y ? 0.0f : ex2(sc[nt][3]);
                rs0 += e0 + e1; rs1 += e2 + e3;
                uint32_t u01 = packhf(e0, e1);
                uint32_t u23 = packhf(e2, e3);
                *reinterpret_cast<uint32_t*>(g_pf + rowA * S_ + cg)       = u01;
                *reinterpret_cast<uint32_t*>(g_pf + (rowA + 8) * S_ + cg) = u23;
                const int fb = (nt & 1) ? 2 : 0;
                pf[nt >> 1][fb]     = u01;
                pf[nt >> 1][fb + 1] = u23;
            }

            // ---- P·V half: single-pass fp16, k-slice h ----
            const uint32_t vbase = base + OFF_VF + (uint32_t)(h * 9216) + kofsV;
            #pragma unroll
            for (int kcp = 0; kcp < 4; ++kcp) {
                #pragma unroll
                for (int ntp = 0; ntp < 4; ++ntp) {
                    uint32_t vf[4];
                    ldsm4t(vf, vbase + (uint32_t)(kcp * 2304 + ntp * 32));
                    mma_f16(ctx[2 * ntp],     pf[kcp], vf[0], vf[1]);
                    mma_f16(ctx[2 * ntp + 1], pf[kcp], vf[2], vf[3]);
                }
            }
        }
    }

    // ---- partial rowsums -> global atomic ----
    rs0 += __shfl_xor_sync(0xffffffffu, rs0, 1);
    rs0 += __shfl_xor_sync(0xffffffffu, rs0, 2);
    rs1 += __shfl_xor_sync(0xffffffffu, rs1, 1);
    rs1 += __shfl_xor_sync(0xffffffffu, rs1, 2);
    __syncthreads();
    float* rsum = reinterpret_cast<float*>(smc + SM_RS);
    if ((lane & 3) == 0) {
        rsum[16 * w + (lane >> 2)]     = rs0;
        rsum[16 * w + (lane >> 2) + 8] = rs1;
    }
    __syncthreads();
    if (tid < BQ) atomicAdd(&g_rowsum[(size_t)b * S_ + q0 + tid], rsum[tid]);

    // ---- partial (unnormalized) ctx -> scratch ----
    float* cp = g_ctxp + ((size_t)z * B_ * S_ + rowA) * D_HD;
    #pragma unroll
    for (int nt = 0; nt < 8; ++nt) {
        int d = nt * 8 + colL;
        *reinterpret_cast<float2*>(cp + d) = make_float2(ctx[nt][0], ctx[nt][1]);
        *reinterpret_cast<float2*>(cp + (size_t)8 * S_ * D_HD / S_ * 0 + 8 * D_HD + d) =
            make_float2(ctx[nt][2], ctx[nt][3]);
    }

    // ---- ticket: second finisher runs the combine+normalize tail ----
    __threadfence();
    if (tid == 0)
        s_ticket = atomicAdd(&g_done[b * (S_ / BQ) + blockIdx.x], 1);
    __syncthreads();
    if (s_ticket != 1) return;
    __threadfence();

    if (tid < BQ) rsum[tid] = 1.0f / g_rowsum[(size_t)b * S_ + q0 + tid];
    __syncthreads();

    // ctx combine + normalize (128 rows x 64 cols)
    {
        const float* c0 = g_ctxp + ((size_t)b * S_ + q0) * D_HD;
        const float* c1 = g_ctxp + ((size_t)B_ * S_ + (size_t)b * S_ + q0) * D_HD;
        float* co = ctx_out + ((size_t)b * S_ + q0) * D_HD;
        #pragma unroll 4
        for (int i = tid; i < BQ * (D_HD / 4); i += NTH) {
            int row = i >> 4;
            int cc  = (i & 15) * 4;
            float4 a = *reinterpret_cast<const float4*>(c0 + (size_t)row * D_HD + cc);
            float4 bb = *reinterpret_cast<const float4*>(c1 + (size_t)row * D_HD + cc);
            float s = rsum[row];
            *reinterpret_cast<float4*>(co + (size_t)row * D_HD + cc) =
                make_float4((a.x + bb.x) * s, (a.y + bb.y) * s,
                            (a.z + bb.z) * s, (a.w + bb.w) * s);
        }
    }

    // attn normalize: pf strip -> fp32
    {
        const __half* pfb = g_pf + ((size_t)b * S_ + q0) * S_;
        float* ab = attn_out + ((size_t)b * S_ + q0) * S_;
        #pragma unroll 4
        for (int i = tid; i < BQ * (S_ / 8); i += NTH) {
            int row = i >> 9;
            int ch  = (i & 511) << 3;
            float s = rsum[row];
            uint4 v = *reinterpret_cast<const uint4*>(pfb + (size_t)row * S_ + ch);
            float2 f0 = __half22float2(*reinterpret_cast<__half2*>(&v.x));
            float2 f1 = __half22float2(*reinterpret_cast<__half2*>(&v.y));
            float2 f2 = __half22float2(*reinterpret_cast<__half2*>(&v.z));
            float2 f3 = __half22float2(*reinterpret_cast<__half2*>(&v.w));
            float4* out = reinterpret_cast<float4*>(ab + (size_t)row * S_ + ch);
            out[0] = make_float4(f0.x * s, f0.y * s, f1.x * s, f1.y * s);
            out[1] = make_float4(f2.x * s, f2.y * s, f3.x * s, f3.y * s);
        }
    }
}

extern "C" void kernel_launch(void* const* d_in, const int* in_sizes, int n_in,
                              void* d_out, int out_size)
{
    const float* Q = (const float*)d_in[0];
    const float* K = (const float*)d_in[1];
    const float* V = (const float*)d_in[2];
    const int* mask = (const int*)d_in[3];

    float* ctx_out  = (float*)d_out;
    float* attn_out = ctx_out + (size_t)B_ * S_ * D_HD;

    static bool attr_set = false;
    if (!attr_set) {
        cudaFuncSetAttribute(attn_hmma_kernel,
                             cudaFuncAttributeMaxDynamicSharedMemorySize, SM_TOT);
        attr_set = true;
    }

    prep_half_kernel<<<(B_ * S_ * D_HD / 4) / 256, 256>>>(K, V);
    dim3 grid(S_ / BQ, B_, KSPLIT);
    attn_hmma_kernel<<<grid, NTH, SM_TOT>>>(Q, mask, ctx_out, attn_out);
}

// round 11
// speedup vs baseline: 1.3581x; 1.3490x over previous
#include <cuda_runtime.h>
#include <cuda_fp16.h>
#include <cstdint>

#define B_   8
#define S_   4096
#define D_HD 64
#define BQ   128
#define BK   128
#define NTH  256
#define NT   (S_ / BK)          // 32 tiles

// Q pre-scale: (1/sqrt(64)) * log2(e)  -> scores arrive in log2 domain
#define QSCALE 0.18033688011112042f

// ---- 2-stage pipelined smem: stage = KF(18432) + VF(18432) + MASK(69632) ----
#define OFF_KF  0
#define OFF_VF  18432
#define OFF_MSK 36864
#define MSK_STRIDE 544          // 512B payload + 32B pad: conflict-free LDS.64
#define STAGE_BYTES (36864 + 128 * MSK_STRIDE)   // 106496
#define SM_RS  (2 * STAGE_BYTES)                 // float[128]
#define SM_TOT (2 * STAGE_BYTES + 512)           // 213504 <= 227KB
#define QS_STRIDE 68

// fp16 K/V in tile-ready layout: [b*S + row][72 halves] (144B row stride)
#define GROW 72
__device__ __align__(16) __half g_kf[(size_t)B_ * S_ * GROW];
__device__ __align__(16) __half g_vf[(size_t)B_ * S_ * GROW];
// unnormalized exp(scores) in fp16: [b*S + q][S]
__device__ __align__(16) __half g_pf[(size_t)B_ * S_ * S_];
__device__ float g_rowsum[(size_t)B_ * S_];

static __device__ __forceinline__ uint32_t smem_u32(const void* p) {
    uint32_t a;
    asm("{ .reg .u64 t; cvta.to.shared.u64 t, %1; cvt.u32.u64 %0, t; }" : "=r"(a) : "l"(p));
    return a;
}
static __device__ __forceinline__ void ldsm4(uint32_t* r, uint32_t addr) {
    asm volatile("ldmatrix.sync.aligned.m8n8.x4.shared.b16 {%0,%1,%2,%3}, [%4];"
                 : "=r"(r[0]), "=r"(r[1]), "=r"(r[2]), "=r"(r[3]) : "r"(addr));
}
static __device__ __forceinline__ void ldsm4t(uint32_t* r, uint32_t addr) {
    asm volatile("ldmatrix.sync.aligned.m8n8.x4.trans.shared.b16 {%0,%1,%2,%3}, [%4];"
                 : "=r"(r[0]), "=r"(r[1]), "=r"(r[2]), "=r"(r[3]) : "r"(addr));
}
static __device__ __forceinline__ void mma_f16(float* c, const uint32_t* a,
                                               uint32_t b0, uint32_t b1) {
    asm volatile("mma.sync.aligned.m16n8k16.row.col.f32.f16.f16.f32 "
                 "{%0,%1,%2,%3}, {%4,%5,%6,%7}, {%8,%9}, {%0,%1,%2,%3};"
                 : "+f"(c[0]), "+f"(c[1]), "+f"(c[2]), "+f"(c[3])
                 : "r"(a[0]), "r"(a[1]), "r"(a[2]), "r"(a[3]), "r"(b0), "r"(b1));
}
static __device__ __forceinline__ uint32_t packhf(float a, float b) {
    __half2 t = __floats2half2_rn(a, b);
    return *reinterpret_cast<uint32_t*>(&t);
}
static __device__ __forceinline__ float ex2(float x) {
    float r;
    asm("ex2.approx.f32 %0, %1;" : "=f"(r) : "f"(x));
    return r;
}

// ---- one-time convert of K/V to fp16 in tile-ready layout ----
__global__ __launch_bounds__(256)
void prep_half_kernel(const float* __restrict__ K, const float* __restrict__ V)
{
    size_t idx = (size_t)blockIdx.x * 256 + threadIdx.x;   // float4 index
    size_t row = idx >> 4;
    int d4 = (int)(idx & 15);
    size_t dst = row * GROW + (size_t)d4 * 4;

    float4 kv = reinterpret_cast<const float4*>(K)[idx];
    *reinterpret_cast<uint2*>(&g_kf[dst]) =
        make_uint2(packhf(kv.x, kv.y), packhf(kv.z, kv.w));
    float4 vv = reinterpret_cast<const float4*>(V)[idx];
    *reinterpret_cast<uint2*>(&g_vf[dst]) =
        make_uint2(packhf(vv.x, vv.y), packhf(vv.z, vv.w));
}

__global__ __launch_bounds__(NTH)
void attn_hmma_kernel(const float* __restrict__ Q,
                      const int*   __restrict__ mask,
                      float* __restrict__ ctx_out)
{
    extern __shared__ char smc[];
    const uint32_t sb = smem_u32(smc);

    const int tid  = threadIdx.x;
    const int w    = tid >> 5;          // warp owns q-rows [16w, 16w+16)
    const int lane = tid & 31;
    const int lrow = lane & 7;
    const int lsub = lane >> 3;
    const int b    = blockIdx.y;
    const int q0   = blockIdx.x * BQ;

    const uint32_t kofsB = (uint32_t)((((lsub & 2) ? 8 : 0) + lrow) * 144 + ((lsub & 1) ? 16 : 0));
    const uint32_t kofsV = (uint32_t)((lrow + ((lsub & 1) ? 8 : 0)) * 144 + ((lsub & 2) ? 16 : 0));

    const uint64_t mgm = (uint64_t)__cvta_generic_to_global(
        mask + ((size_t)b * S_ + q0) * S_);

    // async copy of one k-tile (KF + VF + mask strip) into a stage
    auto issue_copy = [&](int t, int stg) {
        size_t gbase = ((size_t)b * S_ + (size_t)t * BK) * GROW;
        const __half* gp[2] = { g_kf + gbase, g_vf + gbase };
        uint32_t s0 = sb + (uint32_t)stg * STAGE_BYTES;
        #pragma unroll
        for (int a = 0; a < 2; ++a) {
            uint64_t ga = (uint64_t)__cvta_generic_to_global(gp[a]);
            uint32_t sa = s0 + (uint32_t)a * 18432u;
            #pragma unroll
            for (int i = 0; i < 4; ++i) {
                uint32_t o = (uint32_t)(tid + i * NTH) * 16u;
                asm volatile("cp.async.cg.shared.global [%0], [%1], 16;"
                             :: "r"(sa + o), "l"(ga + o));
            }
            if (tid < 128) {
                uint32_t o = (uint32_t)(1024 + tid) * 16u;
                asm volatile("cp.async.cg.shared.global [%0], [%1], 16;"
                             :: "r"(sa + o), "l"(ga + o));
            }
        }
        // mask tile: 128 rows x 512B (32 x 16B chunks per row), padded rows in smem
        uint64_t mg = mgm + (uint64_t)t * (BK * 4);
        uint32_t ms = s0 + OFF_MSK;
        #pragma unroll
        for (int i = 0; i < 16; ++i) {
            int c   = tid + i * NTH;
            int row = c >> 5;
            int off = (c & 31) * 16;
            asm volatile("cp.async.cg.shared.global [%0], [%1], 16;"
                         :: "r"(ms + (uint32_t)(row * MSK_STRIDE + off)),
                            "l"(mg + (uint64_t)row * (S_ * 4) + (uint64_t)off));
        }
        asm volatile("cp.async.commit_group;" ::: "memory");
    };

    // prologue: tile 0 in flight; Q (scaled) staged in stage-1 region
    issue_copy(0, 0);
    {
        float* smf = reinterpret_cast<float*>(smc + STAGE_BYTES);
        const float* Qg = Q + ((size_t)b * S_ + q0) * D_HD;
        #pragma unroll
        for (int it = 0; it < 8; ++it) {
            int idx = (it * NTH + tid) * 4;
            int q = idx >> 6, d = idx & 63;
            float4 v = *reinterpret_cast<const float4*>(Qg + idx);
            float* dst = smf + q * QS_STRIDE + d;
            dst[0] = v.x * QSCALE; dst[1] = v.y * QSCALE;
            dst[2] = v.z * QSCALE; dst[3] = v.w * QSCALE;
        }
    }
    __syncthreads();

    // persistent fp16 Q A-fragments (16 regs)
    uint32_t qf[4][4];
    {
        const float* smf = reinterpret_cast<const float*>(smc + STAGE_BYTES);
        const int r0 = 16 * w + (lane >> 2);
        const int c0 = 2 * (lane & 3);
        #pragma unroll
        for (int kc = 0; kc < 4; ++kc) {
            #pragma unroll
            for (int f = 0; f < 4; ++f) {
                int rr = r0 + ((f & 1) ? 8 : 0);
                int cc = kc * 16 + c0 + ((f & 2) ? 8 : 0);
                float2 v = *reinterpret_cast<const float2*>(smf + rr * QS_STRIDE + cc);
                qf[kc][f] = packhf(v.x, v.y);
            }
        }
    }
    __syncthreads();   // Q staging done; stage-1 free for the pipeline
    issue_copy(1, 1);

    float ctx[8][4];
    #pragma unroll
    for (int i = 0; i < 8; ++i)
        #pragma unroll
        for (int j = 0; j < 4; ++j) ctx[i][j] = 0.0f;
    float rs0 = 0.0f, rs1 = 0.0f;

    const size_t rowA = (size_t)b * S_ + q0 + 16 * w + (lane >> 2);
    const int    colL = 2 * (lane & 3);
    const uint32_t mro = (uint32_t)((16 * w + (lane >> 2)) * MSK_STRIDE + colL * 4);

    for (int t = 0; t < NT; ++t) {
        const int k0 = t << 7;

        if (t < NT - 1)
            asm volatile("cp.async.wait_group 1;" ::: "memory");
        else
            asm volatile("cp.async.wait_group 0;" ::: "memory");
        __syncthreads();                        // tile t fully resident

        const uint32_t stofs = (uint32_t)(t & 1) * STAGE_BYTES;
        const uint32_t base  = sb + stofs;
        const char*    mbp   = smc + stofs + OFF_MSK;

        #pragma unroll
        for (int h = 0; h < 2; ++h) {
            // ---- QK^T half: single-pass fp16 (scores in log2 domain) ----
            float sc[8][4];
            #pragma unroll
            for (int i = 0; i < 8; ++i)
                #pragma unroll
                for (int j = 0; j < 4; ++j) sc[i][j] = 0.0f;

            const uint32_t bbase = base + OFF_KF + (uint32_t)(h * 9216) + kofsB;
            #pragma unroll
            for (int kc = 0; kc < 4; ++kc) {
                #pragma unroll
                for (int ntp = 0; ntp < 4; ++ntp) {
                    uint32_t bfr[4];
                    ldsm4(bfr, bbase + (uint32_t)(ntp * 2304 + kc * 32));
                    mma_f16(sc[2 * ntp],     qf[kc], bfr[0], bfr[1]);
                    mma_f16(sc[2 * ntp + 1], qf[kc], bfr[2], bfr[3]);
                }
            }

            // ---- mask (smem) + ex2 + fp16 scratch write; P frags reuse packs ----
            uint32_t pf[4][4];
            #pragma unroll
            for (int nt = 0; nt < 8; ++nt) {
                const uint32_t mo = mro + (uint32_t)(h * 256 + nt * 32);
                const int2 m0 = *reinterpret_cast<const int2*>(mbp + mo);
                const int2 m1 = *reinterpret_cast<const int2*>(mbp + mo + 8 * MSK_STRIDE);
                const size_t cg = (size_t)(k0 + h * 64 + nt * 8 + colL);
                float e0 = m0.x ? 0.0f : ex2(sc[nt][0]);
                float e1 = m0.y ? 0.0f : ex2(sc[nt][1]);
                float e2 = m1.x ? 0.0f : ex2(sc[nt][2]);
                float e3 = m1.y ? 0.0f : ex2(sc[nt][3]);
                rs0 += e0 + e1; rs1 += e2 + e3;
                uint32_t u01 = packhf(e0, e1);
                uint32_t u23 = packhf(e2, e3);
                *reinterpret_cast<uint32_t*>(g_pf + rowA * S_ + cg)       = u01;
                *reinterpret_cast<uint32_t*>(g_pf + (rowA + 8) * S_ + cg) = u23;
                const int fb = (nt & 1) ? 2 : 0;
                pf[nt >> 1][fb]     = u01;
                pf[nt >> 1][fb + 1] = u23;
            }

            // ---- P·V half: single-pass fp16, k-slice h ----
            const uint32_t vbase = base + OFF_VF + (uint32_t)(h * 9216) + kofsV;
            #pragma unroll
            for (int kcp = 0; kcp < 4; ++kcp) {
                #pragma unroll
                for (int ntp = 0; ntp < 4; ++ntp) {
                    uint32_t vf[4];
                    ldsm4t(vf, vbase + (uint32_t)(kcp * 2304 + ntp * 32));
                    mma_f16(ctx[2 * ntp],     pf[kcp], vf[0], vf[1]);
                    mma_f16(ctx[2 * ntp + 1], pf[kcp], vf[2], vf[3]);
                }
            }
        }

        __syncthreads();                        // all warps done with stage t
        if (t + 2 < NT) issue_copy(t + 2, t & 1);
    }

    // ---- rowsums + normalized ctx ----
    rs0 += __shfl_xor_sync(0xffffffffu, rs0, 1);
    rs0 += __shfl_xor_sync(0xffffffffu, rs0, 2);
    rs1 += __shfl_xor_sync(0xffffffffu, rs1, 1);
    rs1 += __shfl_xor_sync(0xffffffffu, rs1, 2);
    __syncthreads();
    float* rsum = reinterpret_cast<float*>(smc + SM_RS);
    if ((lane & 3) == 0) {
        rsum[16 * w + (lane >> 2)]     = rs0;
        rsum[16 * w + (lane >> 2) + 8] = rs1;
    }
    __syncthreads();
    if (tid < BQ) g_rowsum[(size_t)b * S_ + q0 + tid] = rsum[tid];

    const float inv0 = 1.0f / rsum[16 * w + (lane >> 2)];
    const float inv1 = 1.0f / rsum[16 * w + (lane >> 2) + 8];
    #pragma unroll
    for (int nt = 0; nt < 8; ++nt) {
        int d = nt * 8 + colL;
        *reinterpret_cast<float2*>(ctx_out + rowA * D_HD + d) =
            make_float2(ctx[nt][0] * inv0, ctx[nt][1] * inv0);
        *reinterpret_cast<float2*>(ctx_out + (rowA + 8) * D_HD + d) =
            make_float2(ctx[nt][2] * inv1, ctx[nt][3] * inv1);
    }
}

// normalize fp16 scratch -> fp32 attn output (streams at DRAM roofline)
__global__ void attn_norm_kernel(float* __restrict__ attn)
{
    const size_t n8 = (size_t)B_ * S_ * S_ / 8;
    for (size_t i = (size_t)blockIdx.x * blockDim.x + threadIdx.x;
         i < n8; i += (size_t)gridDim.x * blockDim.x) {
        uint4 v = reinterpret_cast<const uint4*>(g_pf)[i];
        size_t row = i >> 9;                   // (i*8) / S_
        float s = __fdividef(1.0f, g_rowsum[row]);
        float2 f0 = __half22float2(*reinterpret_cast<__half2*>(&v.x));
        float2 f1 = __half22float2(*reinterpret_cast<__half2*>(&v.y));
        float2 f2 = __half22float2(*reinterpret_cast<__half2*>(&v.z));
        float2 f3 = __half22float2(*reinterpret_cast<__half2*>(&v.w));
        float4* out = reinterpret_cast<float4*>(attn + i * 8);
        out[0] = make_float4(f0.x * s, f0.y * s, f1.x * s, f1.y * s);
        out[1] = make_float4(f2.x * s, f2.y * s, f3.x * s, f3.y * s);
    }
}

extern "C" void kernel_launch(void* const* d_in, const int* in_sizes, int n_in,
                              void* d_out, int out_size)
{
    const float* Q = (const float*)d_in[0];
    const float* K = (const float*)d_in[1];
    const float* V = (const float*)d_in[2];
    const int* mask = (const int*)d_in[3];

    float* ctx_out  = (float*)d_out;
    float* attn_out = ctx_out + (size_t)B_ * S_ * D_HD;

    static bool attr_set = false;
    if (!attr_set) {
        cudaFuncSetAttribute(attn_hmma_kernel,
                             cudaFuncAttributeMaxDynamicSharedMemorySize, SM_TOT);
        attr_set = true;
    }

    prep_half_kernel<<<(B_ * S_ * D_HD / 4) / 256, 256>>>(K, V);
    dim3 grid(S_ / BQ, B_);
    attn_hmma_kernel<<<grid, NTH, SM_TOT>>>(Q, mask, ctx_out);
    attn_norm_kernel<<<8192, 256>>>(attn_out);
}

// round 12
// speedup vs baseline: 1.4038x; 1.0336x over previous
#include <cuda_runtime.h>
#include <cuda_fp16.h>
#include <cstdint>

#define B_   8
#define S_   4096
#define D_HD 64
#define BQ   128
#define BK   128
#define NTH  512
#define NT   (S_ / BK)          // 32 tiles

// Q pre-scale: (1/sqrt(64)) * log2(e)  -> scores arrive in log2 domain
#define QSCALE 0.18033688011112042f

// ---- 2-stage pipelined smem: stage = KF(18432) + VF(18432) + MASK(69632) ----
#define OFF_KF  0
#define OFF_VF  18432
#define OFF_MSK 36864
#define MSK_STRIDE 544          // 512B payload + 32B pad: conflict-free LDS.64
#define STAGE_BYTES (36864 + 128 * MSK_STRIDE)   // 106496
#define SM_RS  (2 * STAGE_BYTES)                 // float[2][128]
#define SM_TOT (2 * STAGE_BYTES + 1536)
#define QS_STRIDE 68

// fp16 K/V in tile-ready layout: [b*S + row][72 halves] (144B row stride)
#define GROW 72
__device__ __align__(16) __half g_kf[(size_t)B_ * S_ * GROW];
__device__ __align__(16) __half g_vf[(size_t)B_ * S_ * GROW];
// unnormalized exp(scores) in fp16: [b*S + q][S]
__device__ __align__(16) __half g_pf[(size_t)B_ * S_ * S_];
__device__ float g_rowsum[(size_t)B_ * S_];

static __device__ __forceinline__ uint32_t smem_u32(const void* p) {
    uint32_t a;
    asm("{ .reg .u64 t; cvta.to.shared.u64 t, %1; cvt.u32.u64 %0, t; }" : "=r"(a) : "l"(p));
    return a;
}
static __device__ __forceinline__ void ldsm4(uint32_t* r, uint32_t addr) {
    asm volatile("ldmatrix.sync.aligned.m8n8.x4.shared.b16 {%0,%1,%2,%3}, [%4];"
                 : "=r"(r[0]), "=r"(r[1]), "=r"(r[2]), "=r"(r[3]) : "r"(addr));
}
static __device__ __forceinline__ void ldsm4t(uint32_t* r, uint32_t addr) {
    asm volatile("ldmatrix.sync.aligned.m8n8.x4.trans.shared.b16 {%0,%1,%2,%3}, [%4];"
                 : "=r"(r[0]), "=r"(r[1]), "=r"(r[2]), "=r"(r[3]) : "r"(addr));
}
static __device__ __forceinline__ void mma_f16(float* c, const uint32_t* a,
                                               uint32_t b0, uint32_t b1) {
    asm volatile("mma.sync.aligned.m16n8k16.row.col.f32.f16.f16.f32 "
                 "{%0,%1,%2,%3}, {%4,%5,%6,%7}, {%8,%9}, {%0,%1,%2,%3};"
                 : "+f"(c[0]), "+f"(c[1]), "+f"(c[2]), "+f"(c[3])
                 : "r"(a[0]), "r"(a[1]), "r"(a[2]), "r"(a[3]), "r"(b0), "r"(b1));
}
static __device__ __forceinline__ uint32_t packhf(float a, float b) {
    __half2 t = __floats2half2_rn(a, b);
    return *reinterpret_cast<uint32_t*>(&t);
}
static __device__ __forceinline__ float ex2(float x) {
    float r;
    asm("ex2.approx.f32 %0, %1;" : "=f"(r) : "f"(x));
    return r;
}

// ---- one-time convert of K/V to fp16 in tile-ready layout ----
__global__ __launch_bounds__(256)
void prep_half_kernel(const float* __restrict__ K, const float* __restrict__ V)
{
    size_t idx = (size_t)blockIdx.x * 256 + threadIdx.x;   // float4 index
    size_t row = idx >> 4;
    int d4 = (int)(idx & 15);
    size_t dst = row * GROW + (size_t)d4 * 4;

    float4 kv = reinterpret_cast<const float4*>(K)[idx];
    *reinterpret_cast<uint2*>(&g_kf[dst]) =
        make_uint2(packhf(kv.x, kv.y), packhf(kv.z, kv.w));
    float4 vv = reinterpret_cast<const float4*>(V)[idx];
    *reinterpret_cast<uint2*>(&g_vf[dst]) =
        make_uint2(packhf(vv.x, vv.y), packhf(vv.z, vv.w));
}

__global__ __launch_bounds__(NTH)
void attn_hmma_kernel(const float* __restrict__ Q,
                      const int*   __restrict__ mask,
                      float* __restrict__ ctx_out)
{
    extern __shared__ char smc[];
    const uint32_t sb = smem_u32(smc);

    const int tid  = threadIdx.x;
    const int w    = tid >> 5;
    const int lane = tid & 31;
    const int lrow = lane & 7;
    const int lsub = lane >> 3;
    const int wq   = w >> 1;            // q-row group: rows [16wq, 16wq+16)
    const int h    = w & 1;             // column half: cols [64h, 64h+64)
    const int b    = blockIdx.y;
    const int q0   = blockIdx.x * BQ;

    const uint32_t kofsB = (uint32_t)((((lsub & 2) ? 8 : 0) + lrow) * 144 + ((lsub & 1) ? 16 : 0));
    const uint32_t kofsV = (uint32_t)((lrow + ((lsub & 1) ? 8 : 0)) * 144 + ((lsub & 2) ? 16 : 0));

    const uint64_t mgm = (uint64_t)__cvta_generic_to_global(
        mask + ((size_t)b * S_ + q0) * S_);

    // async copy of one k-tile (KF + VF + mask strip) into a stage
    auto issue_copy = [&](int t, int stg) {
        size_t gbase = ((size_t)b * S_ + (size_t)t * BK) * GROW;
        const __half* gp[2] = { g_kf + gbase, g_vf + gbase };
        uint32_t s0 = sb + (uint32_t)stg * STAGE_BYTES;
        #pragma unroll
        for (int a = 0; a < 2; ++a) {
            uint64_t ga = (uint64_t)__cvta_generic_to_global(gp[a]);
            uint32_t sa = s0 + (uint32_t)a * 18432u;
            {
                uint32_t o = (uint32_t)tid * 16u;
                asm volatile("cp.async.cg.shared.global [%0], [%1], 16;"
                             :: "r"(sa + o), "l"(ga + o));
                o += (uint32_t)NTH * 16u;
                asm volatile("cp.async.cg.shared.global [%0], [%1], 16;"
                             :: "r"(sa + o), "l"(ga + o));
            }
            if (tid < 128) {
                uint32_t o = (uint32_t)(1024 + tid) * 16u;
                asm volatile("cp.async.cg.shared.global [%0], [%1], 16;"
                             :: "r"(sa + o), "l"(ga + o));
            }
        }
        // mask tile: 128 rows x 512B (32 x 16B chunks per row), padded rows
        uint64_t mg = mgm + (uint64_t)t * (BK * 4);
        uint32_t ms = s0 + OFF_MSK;
        #pragma unroll
        for (int i = 0; i < 8; ++i) {
            int c   = tid + i * NTH;
            int row = c >> 5;
            int off = (c & 31) * 16;
            asm volatile("cp.async.cg.shared.global [%0], [%1], 16;"
                         :: "r"(ms + (uint32_t)(row * MSK_STRIDE + off)),
                            "l"(mg + (uint64_t)row * (S_ * 4) + (uint64_t)off));
        }
        asm volatile("cp.async.commit_group;" ::: "memory");
    };

    // prologue: tile 0 in flight; Q (scaled) staged in stage-1 region
    issue_copy(0, 0);
    {
        float* smf = reinterpret_cast<float*>(smc + STAGE_BYTES);
        const float* Qg = Q + ((size_t)b * S_ + q0) * D_HD;
        #pragma unroll
        for (int it = 0; it < 4; ++it) {
            int idx = (it * NTH + tid) * 4;
            int q = idx >> 6, d = idx & 63;
            float4 v = *reinterpret_cast<const float4*>(Qg + idx);
            float* dst = smf + q * QS_STRIDE + d;
            dst[0] = v.x * QSCALE; dst[1] = v.y * QSCALE;
            dst[2] = v.z * QSCALE; dst[3] = v.w * QSCALE;
        }
    }
    __syncthreads();

    // persistent fp16 Q A-fragments (16 regs)
    uint32_t qf[4][4];
    {
        const float* smf = reinterpret_cast<const float*>(smc + STAGE_BYTES);
        const int r0 = 16 * wq + (lane >> 2);
        const int c0 = 2 * (lane & 3);
        #pragma unroll
        for (int kc = 0; kc < 4; ++kc) {
            #pragma unroll
            for (int f = 0; f < 4; ++f) {
                int rr = r0 + ((f & 1) ? 8 : 0);
                int cc = kc * 16 + c0 + ((f & 2) ? 8 : 0);
                float2 v = *reinterpret_cast<const float2*>(smf + rr * QS_STRIDE + cc);
                qf[kc][f] = packhf(v.x, v.y);
            }
        }
    }
    __syncthreads();   // Q staging done; stage-1 free for the pipeline
    issue_copy(1, 1);

    float ctx[8][4];
    #pragma unroll
    for (int i = 0; i < 8; ++i)
        #pragma unroll
        for (int j = 0; j < 4; ++j) ctx[i][j] = 0.0f;
    float rs0 = 0.0f, rs1 = 0.0f;

    const size_t rowA = (size_t)b * S_ + q0 + 16 * wq + (lane >> 2);
    const int    colL = 2 * (lane & 3);
    const uint32_t mro = (uint32_t)((16 * wq + (lane >> 2)) * MSK_STRIDE +
                                    (h * 64 + colL) * 4);

    for (int t = 0; t < NT; ++t) {
        const int k0 = t << 7;

        if (t < NT - 1)
            asm volatile("cp.async.wait_group 1;" ::: "memory");
        else
            asm volatile("cp.async.wait_group 0;" ::: "memory");
        __syncthreads();                        // tile t fully resident

        const uint32_t stofs = (uint32_t)(t & 1) * STAGE_BYTES;
        const uint32_t base  = sb + stofs;
        const char*    mbp   = smc + stofs + OFF_MSK;

        // ---- QK^T (this warp's 64-col half): single-pass fp16 ----
        float sc[8][4];
        #pragma unroll
        for (int i = 0; i < 8; ++i)
            #pragma unroll
            for (int j = 0; j < 4; ++j) sc[i][j] = 0.0f;

        const uint32_t bbase = base + OFF_KF + (uint32_t)(h * 9216) + kofsB;
        #pragma unroll
        for (int kc = 0; kc < 4; ++kc) {
            #pragma unroll
            for (int ntp = 0; ntp < 4; ++ntp) {
                uint32_t bfr[4];
                ldsm4(bfr, bbase + (uint32_t)(ntp * 2304 + kc * 32));
                mma_f16(sc[2 * ntp],     qf[kc], bfr[0], bfr[1]);
                mma_f16(sc[2 * ntp + 1], qf[kc], bfr[2], bfr[3]);
            }
        }

        // ---- mask (smem) + ex2 + fp16 scratch write; P frags reuse packs ----
        uint32_t pf[4][4];
        #pragma unroll
        for (int nt = 0; nt < 8; ++nt) {
            const uint32_t mo = mro + (uint32_t)(nt * 32);
            const int2 m0 = *reinterpret_cast<const int2*>(mbp + mo);
            const int2 m1 = *reinterpret_cast<const int2*>(mbp + mo + 8 * MSK_STRIDE);
            const size_t cg = (size_t)(k0 + h * 64 + nt * 8 + colL);
            float e0 = m0.x ? 0.0f : ex2(sc[nt][0]);
            float e1 = m0.y ? 0.0f : ex2(sc[nt][1]);
            float e2 = m1.x ? 0.0f : ex2(sc[nt][2]);
            float e3 = m1.y ? 0.0f : ex2(sc[nt][3]);
            rs0 += e0 + e1; rs1 += e2 + e3;
            uint32_t u01 = packhf(e0, e1);
            uint32_t u23 = packhf(e2, e3);
            *reinterpret_cast<uint32_t*>(g_pf + rowA * S_ + cg)       = u01;
            *reinterpret_cast<uint32_t*>(g_pf + (rowA + 8) * S_ + cg) = u23;
            const int fb = (nt & 1) ? 2 : 0;
            pf[nt >> 1][fb]     = u01;
            pf[nt >> 1][fb + 1] = u23;
        }

        // ---- P·V (this warp's 64-k slice), full 64 d columns ----
        const uint32_t vbase = base + OFF_VF + (uint32_t)(h * 9216) + kofsV;
        #pragma unroll
        for (int kcp = 0; kcp < 4; ++kcp) {
            #pragma unroll
            for (int ntp = 0; ntp < 4; ++ntp) {
                uint32_t vf[4];
                ldsm4t(vf, vbase + (uint32_t)(kcp * 2304 + ntp * 32));
                mma_f16(ctx[2 * ntp],     pf[kcp], vf[0], vf[1]);
                mma_f16(ctx[2 * ntp + 1], pf[kcp], vf[2], vf[3]);
            }
        }

        __syncthreads();                        // all warps done with stage t
        if (t + 2 < NT) issue_copy(t + 2, t & 1);
    }

    // ---- rowsums (per half) + cross-half ctx combine ----
    rs0 += __shfl_xor_sync(0xffffffffu, rs0, 1);
    rs0 += __shfl_xor_sync(0xffffffffu, rs0, 2);
    rs1 += __shfl_xor_sync(0xffffffffu, rs1, 1);
    rs1 += __shfl_xor_sync(0xffffffffu, rs1, 2);

    float* rsum = reinterpret_cast<float*>(smc + SM_RS);    // [2][128]
    float* cbuf = reinterpret_cast<float*>(smc);            // reuse stage0: [128][68]
    const int r = 16 * wq + (lane >> 2);
    __syncthreads();   // all warps done with stage buffers
    if ((lane & 3) == 0) {
        rsum[h * 128 + r]     = rs0;
        rsum[h * 128 + r + 8] = rs1;
    }
    if (h == 1) {
        #pragma unroll
        for (int nt = 0; nt < 8; ++nt) {
            int d = nt * 8 + colL;
            *reinterpret_cast<float2*>(cbuf + r * 68 + d) =
                make_float2(ctx[nt][0], ctx[nt][1]);
            *reinterpret_cast<float2*>(cbuf + (r + 8) * 68 + d) =
                make_float2(ctx[nt][2], ctx[nt][3]);
        }
    }
    __syncthreads();
    if (tid < BQ) g_rowsum[(size_t)b * S_ + q0 + tid] = rsum[tid] + rsum[128 + tid];

    if (h == 0) {
        const float inv0 = 1.0f / (rsum[r] + rsum[128 + r]);
        const float inv1 = 1.0f / (rsum[r + 8] + rsum[128 + r + 8]);
        #pragma unroll
        for (int nt = 0; nt < 8; ++nt) {
            int d = nt * 8 + colL;
            float2 o0 = *reinterpret_cast<const float2*>(cbuf + r * 68 + d);
            float2 o1 = *reinterpret_cast<const float2*>(cbuf + (r + 8) * 68 + d);
            *reinterpret_cast<float2*>(ctx_out + rowA * D_HD + d) =
                make_float2((ctx[nt][0] + o0.x) * inv0, (ctx[nt][1] + o0.y) * inv0);
            *reinterpret_cast<float2*>(ctx_out + (rowA + 8) * D_HD + d) =
                make_float2((ctx[nt][2] + o1.x) * inv1, (ctx[nt][3] + o1.y) * inv1);
        }
    }
}

// normalize fp16 scratch -> fp32 attn output (streams at DRAM roofline)
__global__ void attn_norm_kernel(float* __restrict__ attn)
{
    const size_t n8 = (size_t)B_ * S_ * S_ / 8;
    for (size_t i = (size_t)blockIdx.x * blockDim.x + threadIdx.x;
         i < n8; i += (size_t)gridDim.x * blockDim.x) {
        uint4 v = reinterpret_cast<const uint4*>(g_pf)[i];
        size_t row = i >> 9;                   // (i*8) / S_
        float s = __fdividef(1.0f, g_rowsum[row]);
        float2 f0 = __half22float2(*reinterpret_cast<__half2*>(&v.x));
        float2 f1 = __half22float2(*reinterpret_cast<__half2*>(&v.y));
        float2 f2 = __half22float2(*reinterpret_cast<__half2*>(&v.z));
        float2 f3 = __half22float2(*reinterpret_cast<__half2*>(&v.w));
        float4* out = reinterpret_cast<float4*>(attn + i * 8);
        out[0] = make_float4(f0.x * s, f0.y * s, f1.x * s, f1.y * s);
        out[1] = make_float4(f2.x * s, f2.y * s, f3.x * s, f3.y * s);
    }
}

extern "C" void kernel_launch(void* const* d_in, const int* in_sizes, int n_in,
                              void* d_out, int out_size)
{
    const float* Q = (const float*)d_in[0];
    const float* K = (const float*)d_in[1];
    const float* V = (const float*)d_in[2];
    const int* mask = (const int*)d_in[3];

    float* ctx_out  = (float*)d_out;
    float* attn_out = ctx_out + (size_t)B_ * S_ * D_HD;

    static bool attr_set = false;
    if (!attr_set) {
        cudaFuncSetAttribute(attn_hmma_kernel,
                             cudaFuncAttributeMaxDynamicSharedMemorySize, SM_TOT);
        attr_set = true;
    }

    prep_half_kernel<<<(B_ * S_ * D_HD / 4) / 256, 256>>>(K, V);
    dim3 grid(S_ / BQ, B_);
    attn_hmma_kernel<<<grid, NTH, SM_TOT>>>(Q, mask, ctx_out);
    attn_norm_kernel<<<8192, 256>>>(attn_out);
}